// round 10
// baseline (speedup 1.0000x reference)
#include <cuda_runtime.h>
#include <math.h>
#include <stdint.h>

#define N_NODES 50000
#define N_EDGES 1600000
#define HIDDIM 128
#define NFEAT 128
#define NGAUSS 64

__device__ float g_h[(size_t)N_NODES * NFEAT];
__device__ float g_agg[(size_t)N_NODES * NFEAT];
__device__ float g_tmp[(size_t)N_NODES * HIDDIM];
__device__ int g_cnt[N_NODES];
__device__ int g_off[N_NODES];
__device__ int g_perm[N_EDGES];

__device__ __forceinline__ float sspf(float v) {
    return fmaxf(v, 0.0f) + log1pf(expf(-fabsf(v))) - 0.69314718055994531f;
}

__device__ __forceinline__ uint32_t f2tf32(float f) {
    uint32_t r;
    asm("cvt.rna.tf32.f32 %0, %1;" : "=r"(r) : "f"(f));
    return r;
}

__device__ __forceinline__ void mma_tf32(float d[4], const uint32_t a[4],
                                         uint32_t b0, uint32_t b1) {
    asm volatile(
        "mma.sync.aligned.m16n8k8.row.col.f32.tf32.tf32.f32 "
        "{%0,%1,%2,%3}, {%4,%5,%6,%7}, {%8,%9}, {%0,%1,%2,%3};"
        : "+f"(d[0]), "+f"(d[1]), "+f"(d[2]), "+f"(d[3])
        : "r"(a[0]), "r"(a[1]), "r"(a[2]), "r"(a[3]), "r"(b0), "r"(b1));
}

__device__ __forceinline__ void red1(float* p, float v) {
    asm volatile("red.global.add.f32 [%0], %1;" ::"l"(p), "f"(v) : "memory");
}

__device__ __forceinline__ void gbar(int id) {
    asm volatile("bar.sync %0, 128;" ::"r"(id) : "memory");
}

#define LDA_EA 68
#define LDA_TS 132
#define LDW 136
#define TEDGE 32

// ---------------------------------------------------------------------------
// Sorting pipeline: counting sort of edges by dst.
// ---------------------------------------------------------------------------
__global__ void hist_kernel(const int* __restrict__ dst) {
    int e = blockIdx.x * blockDim.x + threadIdx.x;
    if (e < N_EDGES) atomicAdd(&g_cnt[dst[e]], 1);
}

__global__ __launch_bounds__(1024) void scan_kernel() {
    __shared__ int wsum[32];
    const int t = threadIdx.x;
    const int C = (N_NODES + 1023) / 1024;  // 49
    const int base = t * C;
    int s = 0;
    for (int i = 0; i < C; i++) {
        int idx = base + i;
        if (idx < N_NODES) s += g_cnt[idx];
    }
    int lane = t & 31, w = t >> 5;
    int v = s;
#pragma unroll
    for (int o = 1; o < 32; o <<= 1) {
        int n = __shfl_up_sync(0xffffffffu, v, o);
        if (lane >= o) v += n;
    }
    if (lane == 31) wsum[w] = v;
    __syncthreads();
    if (w == 0) {
        int x = wsum[lane];
#pragma unroll
        for (int o = 1; o < 32; o <<= 1) {
            int n = __shfl_up_sync(0xffffffffu, x, o);
            if (lane >= o) x += n;
        }
        wsum[lane] = x;
    }
    __syncthreads();
    int excl = v - s + (w > 0 ? wsum[w - 1] : 0);
    for (int i = 0; i < C; i++) {
        int idx = base + i;
        if (idx < N_NODES) {
            int c = g_cnt[idx];
            g_off[idx] = excl;
            excl += c;
        }
    }
}

__global__ void scatter_kernel(const int* __restrict__ dst) {
    int e = blockIdx.x * blockDim.x + threadIdx.x;
    if (e < N_EDGES) {
        int d = dst[e];
        int p = atomicAdd(&g_off[d], 1);
        g_perm[p] = e;
    }
}

// ---------------------------------------------------------------------------
// Node GEMM, tf32 tensor cores
// ---------------------------------------------------------------------------
template <int ACT, int BIAS>
__global__ __launch_bounds__(512) void gemm128_tf32_kernel(
    const float* __restrict__ A, const float* __restrict__ W,
    const float* __restrict__ bias, float* __restrict__ out, int M) {
    extern __shared__ uint32_t smu[];
    uint32_t* As = smu;
    uint32_t* Ws = As + 128 * LDA_TS;
    float* bs = (float*)(Ws + 128 * LDW);

    const int t = threadIdx.x;
    const int row0 = blockIdx.x * 128;
    const int lane = t & 31, warp = t >> 5;
    const int gid = lane >> 2, tid4 = lane & 3;
    const int wr = warp & 3, cg = warp >> 2;
    const int r0 = wr * 32, n0c = cg * 32;

    for (int i = t; i < 128 * 32; i += 512) {
        int r = i >> 5, c4 = i & 31;
        float4 v = ((const float4*)(W + (size_t)r * 128))[c4];
        uint32_t* dst = Ws + r * LDW + c4 * 4;
        dst[0] = f2tf32(v.x);
        dst[1] = f2tf32(v.y);
        dst[2] = f2tf32(v.z);
        dst[3] = f2tf32(v.w);
    }
    for (int i = t; i < 128 * 32; i += 512) {
        int r = i >> 5, c4 = i & 31;
        int rg = row0 + r;
        float4 v = make_float4(0.f, 0.f, 0.f, 0.f);
        if (rg < M) v = ((const float4*)(A + (size_t)rg * 128))[c4];
        uint32_t* dst = As + r * LDA_TS + c4 * 4;
        dst[0] = f2tf32(v.x);
        dst[1] = f2tf32(v.y);
        dst[2] = f2tf32(v.z);
        dst[3] = f2tf32(v.w);
    }
    if (t < 128) bs[t] = BIAS ? bias[t] : 0.0f;
    __syncthreads();

    float acc[2][4][4];
#pragma unroll
    for (int mi = 0; mi < 2; mi++)
#pragma unroll
        for (int ni = 0; ni < 4; ni++) {
            int col = n0c + ni * 8 + 2 * tid4;
            acc[mi][ni][0] = bs[col];
            acc[mi][ni][1] = bs[col + 1];
            acc[mi][ni][2] = bs[col];
            acc[mi][ni][3] = bs[col + 1];
        }
#pragma unroll
    for (int k0 = 0; k0 < 128; k0 += 8) {
        uint32_t afr[2][4];
#pragma unroll
        for (int mi = 0; mi < 2; mi++) {
            int ra = r0 + mi * 16 + gid;
            afr[mi][0] = As[ra * LDA_TS + k0 + tid4];
            afr[mi][1] = As[(ra + 8) * LDA_TS + k0 + tid4];
            afr[mi][2] = As[ra * LDA_TS + k0 + tid4 + 4];
            afr[mi][3] = As[(ra + 8) * LDA_TS + k0 + tid4 + 4];
        }
#pragma unroll
        for (int ni = 0; ni < 4; ni++) {
            int nn = n0c + ni * 8 + gid;
            uint32_t bf0 = Ws[(k0 + tid4) * LDW + nn];
            uint32_t bf1 = Ws[(k0 + tid4 + 4) * LDW + nn];
            mma_tf32(acc[0][ni], afr[0], bf0, bf1);
            mma_tf32(acc[1][ni], afr[1], bf0, bf1);
        }
    }

#pragma unroll
    for (int mi = 0; mi < 2; mi++) {
#pragma unroll
        for (int half = 0; half < 2; half++) {
            int rg = row0 + r0 + mi * 16 + gid + half * 8;
            if (rg >= M) continue;
            float* orow = out + (size_t)rg * 128;
#pragma unroll
            for (int ni = 0; ni < 4; ni++) {
                int col = n0c + ni * 8 + 2 * tid4;
                float v0 = acc[mi][ni][half * 2 + 0];
                float v1 = acc[mi][ni][half * 2 + 1];
                if (ACT == 1) {
                    v0 = sspf(v0);
                    v1 = sspf(v1);
                }
                *(float2*)(orow + col) = make_float2(v0, v1);
            }
        }
    }
}

// ---------------------------------------------------------------------------
// Fused edge kernel: tf32 MMA, 4 groups of 4 warps, edges consumed in
// dst-sorted order via g_perm. Epilogue does a run-reduction over equal-dst
// rows in registers and emits one red.global.add.f32 per run per lane.
// ---------------------------------------------------------------------------
__global__ __launch_bounds__(512, 1) void edge_fused_kernel(
    const float* __restrict__ edge_attr, const int* __restrict__ eidx,
    const float* __restrict__ elen, const float* __restrict__ w1,
    const float* __restrict__ b1, const float* __restrict__ w2,
    const float* __restrict__ b2) {
    extern __shared__ uint32_t smu[];
    uint32_t* W1s = smu;                         // 64*136
    uint32_t* W2s = W1s + 64 * LDW;              // 128*136
    uint32_t* EAsA = W2s + 128 * LDW;            // 4*32*68
    uint32_t* tssA = EAsA + 4 * TEDGE * LDA_EA;  // 4*32*132
    float* b1s = (float*)(tssA + 4 * TEDGE * LDA_TS);  // 128
    float* b2s = b1s + 128;                            // 128
    float* CsA = b2s + 128;                            // 4*32
    int* ssA = (int*)(CsA + 4 * TEDGE);                // 4*32
    int* dsA = ssA + 4 * TEDGE;                        // 4*32
    int* psA = dsA + 4 * TEDGE;                        // 4*32
    unsigned* hdmA = (unsigned*)(psA + 4 * TEDGE);     // 4

    const int t = threadIdx.x;
    const int lane = t & 31, warp = t >> 5;
    const int g = warp >> 2;
    const int w4 = warp & 3;
    const int tg = t & 127;
    const int gid = lane >> 2, tid4 = lane & 3;
    const int n0c = w4 * 32;
    const int* srcp = eidx;
    const int* dstp = eidx + N_EDGES;

    uint32_t* EAs = EAsA + g * TEDGE * LDA_EA;
    uint32_t* tss = tssA + g * TEDGE * LDA_TS;
    float* tssf = (float*)tss;
    float* Cs = CsA + g * TEDGE;
    int* ss = ssA + g * TEDGE;
    int* ds = dsA + g * TEDGE;
    int* ps = psA + g * TEDGE;
    const int bid = 1 + g;

    // One-time weight staging
    for (int i = t; i < 64 * 32; i += 512) {
        int r = i >> 5, c4 = i & 31;
        float4 v = ((const float4*)(w1 + (size_t)r * 128))[c4];
        uint32_t* dstw = W1s + r * LDW + c4 * 4;
        dstw[0] = f2tf32(v.x);
        dstw[1] = f2tf32(v.y);
        dstw[2] = f2tf32(v.z);
        dstw[3] = f2tf32(v.w);
    }
    for (int i = t; i < 128 * 32; i += 512) {
        int r = i >> 5, c4 = i & 31;
        float4 v = ((const float4*)(w2 + (size_t)r * 128))[c4];
        uint32_t* dstw = W2s + r * LDW + c4 * 4;
        dstw[0] = f2tf32(v.x);
        dstw[1] = f2tf32(v.y);
        dstw[2] = f2tf32(v.z);
        dstw[3] = f2tf32(v.w);
    }
    if (t < 128) {
        b1s[t] = b1[t];
        b2s[t] = b2[t];
    }
    __syncthreads();

    const int ntiles = N_EDGES / TEDGE;  // 50000
    const int stride = 4 * gridDim.x;
    for (int tile = blockIdx.x * 4 + g; tile < ntiles; tile += stride) {
        const int e0 = tile * TEDGE;
        gbar(bid);

        if (tg < TEDGE) {
            int pe = g_perm[e0 + tg];
            ps[tg] = pe;
            ss[tg] = srcp[pe];
            ds[tg] = dstp[pe];
            float l = elen[pe];
            float c = 0.5f * (cosf(l * 0.31415926535897932f) + 1.0f);
            if (!(l <= 10.0f && l >= 0.0f)) c = 0.0f;
            Cs[tg] = c;
        }
        gbar(bid);

        // head mask (warp 0 of group); EA gather via perm
        if (w4 == 0) {
            bool head = (lane == 0) || (ds[lane] != ds[lane - 1]);
            unsigned m = __ballot_sync(0xffffffffu, head);
            if (lane == 0) hdmA[g] = m;
        }
        for (int i = tg; i < TEDGE * 16; i += 128) {
            int r = i >> 4, c4 = i & 15;
            float4 v = ((const float4*)(edge_attr + (size_t)ps[r] * 64))[c4];
            uint32_t* dstw = EAs + r * LDA_EA + c4 * 4;
            dstw[0] = f2tf32(v.x);
            dstw[1] = f2tf32(v.y);
            dstw[2] = f2tf32(v.z);
            dstw[3] = f2tf32(v.w);
        }
        gbar(bid);

        float acc[2][4][4];

        // ---- Stage 1: ts = ssp(EA @ W1 + b1), K=64 ----
#pragma unroll
        for (int mi = 0; mi < 2; mi++)
#pragma unroll
            for (int ni = 0; ni < 4; ni++) {
                int col = n0c + ni * 8 + 2 * tid4;
                acc[mi][ni][0] = b1s[col];
                acc[mi][ni][1] = b1s[col + 1];
                acc[mi][ni][2] = b1s[col];
                acc[mi][ni][3] = b1s[col + 1];
            }
#pragma unroll
        for (int k0 = 0; k0 < 64; k0 += 8) {
            uint32_t afr[2][4];
#pragma unroll
            for (int mi = 0; mi < 2; mi++) {
                int ra = mi * 16 + gid;
                afr[mi][0] = EAs[ra * LDA_EA + k0 + tid4];
                afr[mi][1] = EAs[(ra + 8) * LDA_EA + k0 + tid4];
                afr[mi][2] = EAs[ra * LDA_EA + k0 + tid4 + 4];
                afr[mi][3] = EAs[(ra + 8) * LDA_EA + k0 + tid4 + 4];
            }
#pragma unroll
            for (int ni = 0; ni < 4; ni++) {
                int nn = n0c + ni * 8 + gid;
                uint32_t bf0 = W1s[(k0 + tid4) * LDW + nn];
                uint32_t bf1 = W1s[(k0 + tid4 + 4) * LDW + nn];
                mma_tf32(acc[0][ni], afr[0], bf0, bf1);
                mma_tf32(acc[1][ni], afr[1], bf0, bf1);
            }
        }
#pragma unroll
        for (int mi = 0; mi < 2; mi++) {
            int ra = mi * 16 + gid;
#pragma unroll
            for (int ni = 0; ni < 4; ni++) {
                int col = n0c + ni * 8 + 2 * tid4;
                uint2 lo = make_uint2(f2tf32(sspf(acc[mi][ni][0])),
                                      f2tf32(sspf(acc[mi][ni][1])));
                uint2 hi = make_uint2(f2tf32(sspf(acc[mi][ni][2])),
                                      f2tf32(sspf(acc[mi][ni][3])));
                *(uint2*)(tss + ra * LDA_TS + col) = lo;
                *(uint2*)(tss + (ra + 8) * LDA_TS + col) = hi;
            }
        }
        gbar(bid);

        // ---- Stage 2: W = ts @ W2 + b2, K=128 ----
#pragma unroll
        for (int mi = 0; mi < 2; mi++)
#pragma unroll
            for (int ni = 0; ni < 4; ni++) {
                int col = n0c + ni * 8 + 2 * tid4;
                acc[mi][ni][0] = b2s[col];
                acc[mi][ni][1] = b2s[col + 1];
                acc[mi][ni][2] = b2s[col];
                acc[mi][ni][3] = b2s[col + 1];
            }
#pragma unroll
        for (int k0 = 0; k0 < 128; k0 += 8) {
            uint32_t afr[2][4];
#pragma unroll
            for (int mi = 0; mi < 2; mi++) {
                int ra = mi * 16 + gid;
                afr[mi][0] = tss[ra * LDA_TS + k0 + tid4];
                afr[mi][1] = tss[(ra + 8) * LDA_TS + k0 + tid4];
                afr[mi][2] = tss[ra * LDA_TS + k0 + tid4 + 4];
                afr[mi][3] = tss[(ra + 8) * LDA_TS + k0 + tid4 + 4];
            }
#pragma unroll
            for (int ni = 0; ni < 4; ni++) {
                int nn = n0c + ni * 8 + gid;
                uint32_t bf0 = W2s[(k0 + tid4) * LDW + nn];
                uint32_t bf1 = W2s[(k0 + tid4 + 4) * LDW + nn];
                mma_tf32(acc[0][ni], afr[0], bf0, bf1);
                mma_tf32(acc[1][ni], afr[1], bf0, bf1);
            }
        }
        gbar(bid);

        // Stage acc*C into tss (fp32, fragment layout)
#pragma unroll
        for (int mi = 0; mi < 2; mi++) {
            int rA = mi * 16 + gid;
            int rB = rA + 8;
            float CA = Cs[rA], CB = Cs[rB];
#pragma unroll
            for (int ni = 0; ni < 4; ni++) {
                int col = n0c + ni * 8 + 2 * tid4;
                *(float2*)(tssf + rA * LDA_TS + col) =
                    make_float2(acc[mi][ni][0] * CA, acc[mi][ni][1] * CA);
                *(float2*)(tssf + rB * LDA_TS + col) =
                    make_float2(acc[mi][ni][2] * CB, acc[mi][ni][3] * CB);
            }
        }
        gbar(bid);

        // Phase A: multiply in place by gathered h[src] (coalesced rows)
#pragma unroll
        for (int it = 0; it < 8; it++) {
            int idx = it * 128 + tg;
            int r = idx >> 5, c4 = idx & 31;
            float4 w4v = *(const float4*)(tssf + r * LDA_TS + c4 * 4);
            const float4 h4 =
                *(const float4*)(g_h + (size_t)ss[r] * 128 + c4 * 4);
            w4v.x *= h4.x;
            w4v.y *= h4.y;
            w4v.z *= h4.z;
            w4v.w *= h4.w;
            *(float4*)(tssf + r * LDA_TS + c4 * 4) = w4v;
        }
        gbar(bid);

        // Phase B: run-reduction over equal-dst rows; one red per run per lane
        {
            const unsigned mask = hdmA[g];
            const int col = n0c + lane;
            float vs[TEDGE];
#pragma unroll
            for (int r = 0; r < TEDGE; r++) vs[r] = tssf[r * LDA_TS + col];
            float acr = vs[0];
            int curd = ds[0];
#pragma unroll
            for (int r = 1; r < TEDGE; r++) {
                if ((mask >> r) & 1u) {
                    red1(g_agg + (size_t)curd * 128 + col, acr);
                    curd = ds[r];
                    acr = vs[r];
                } else {
                    acr += vs[r];
                }
            }
            red1(g_agg + (size_t)curd * 128 + col, acr);
        }
    }
}

__global__ void zero_kernel(float4* p, int n4) {
    int i = blockIdx.x * blockDim.x + threadIdx.x;
    if (i < n4) p[i] = make_float4(0.f, 0.f, 0.f, 0.f);
}

__global__ void zero_int_kernel(int* p, int n) {
    int i = blockIdx.x * blockDim.x + threadIdx.x;
    if (i < n) p[i] = 0;
}

extern "C" void kernel_launch(void* const* d_in, const int* in_sizes, int n_in,
                              void* d_out, int out_size) {
    const float* x = (const float*)d_in[0];
    const int* eidx = (const int*)d_in[1];
    const float* elen = (const float*)d_in[2];
    const float* eattr = (const float*)d_in[3];
    const float* lin1_w = (const float*)d_in[4];
    const float* nn_w1 = (const float*)d_in[5];
    const float* nn_b1 = (const float*)d_in[6];
    const float* nn_w2 = (const float*)d_in[7];
    const float* nn_b2 = (const float*)d_in[8];
    const float* lin2_w = (const float*)d_in[9];
    const float* lin2_b = (const float*)d_in[10];
    const float* lin_w = (const float*)d_in[11];
    const float* lin_b = (const float*)d_in[12];
    float* out = (float*)d_out;
    const int* dstp = eidx + N_EDGES;

    float *h_p, *agg_p, *tmp_p;
    int* cnt_p;
    cudaGetSymbolAddress((void**)&h_p, g_h);
    cudaGetSymbolAddress((void**)&agg_p, g_agg);
    cudaGetSymbolAddress((void**)&tmp_p, g_tmp);
    cudaGetSymbolAddress((void**)&cnt_p, g_cnt);

    const size_t ngemm_smem =
        (size_t)(128 * LDA_TS + 128 * LDW) * 4 + 128 * sizeof(float);
    const size_t edge_smem =
        (size_t)(64 * LDW + 128 * LDW + 4 * TEDGE * LDA_EA +
                 4 * TEDGE * LDA_TS) *
            4 +
        (size_t)(2 * 128 + 4 * TEDGE) * sizeof(float) +
        (size_t)(12 * TEDGE + 4) * sizeof(int);

    cudaFuncSetAttribute(gemm128_tf32_kernel<0, 0>,
                         cudaFuncAttributeMaxDynamicSharedMemorySize,
                         (int)ngemm_smem);
    cudaFuncSetAttribute(gemm128_tf32_kernel<1, 1>,
                         cudaFuncAttributeMaxDynamicSharedMemorySize,
                         (int)ngemm_smem);
    cudaFuncSetAttribute(gemm128_tf32_kernel<0, 1>,
                         cudaFuncAttributeMaxDynamicSharedMemorySize,
                         (int)ngemm_smem);
    cudaFuncSetAttribute(edge_fused_kernel,
                         cudaFuncAttributeMaxDynamicSharedMemorySize,
                         (int)edge_smem);

    const int gridN = (N_NODES + 127) / 128;  // 391

    // Sort edges by dst (counting sort)
    zero_int_kernel<<<(N_NODES + 255) / 256, 256>>>(cnt_p, N_NODES);
    hist_kernel<<<(N_EDGES + 255) / 256, 256>>>(dstp);
    scan_kernel<<<1, 1024>>>();
    scatter_kernel<<<(N_EDGES + 255) / 256, 256>>>(dstp);

    // h = x @ lin1_w ; agg = 0
    gemm128_tf32_kernel<0, 0><<<gridN, 512, ngemm_smem>>>(x, lin1_w, nullptr,
                                                          h_p, N_NODES);
    {
        int n4 = N_NODES * NFEAT / 4;
        zero_kernel<<<(n4 + 255) / 256, 256>>>((float4*)agg_p, n4);
    }
    // fused edge MLP + envelope + gather + run-reduced scatter
    edge_fused_kernel<<<148, 512, edge_smem>>>(eattr, eidx, elen, nn_w1, nn_b1,
                                               nn_w2, nn_b2);
    gemm128_tf32_kernel<1, 1><<<gridN, 512, ngemm_smem>>>(agg_p, lin2_w,
                                                          lin2_b, tmp_p,
                                                          N_NODES);
    gemm128_tf32_kernel<0, 1><<<gridN, 512, ngemm_smem>>>(tmp_p, lin_w, lin_b,
                                                          out, N_NODES);
}

// round 11
// speedup vs baseline: 1.4591x; 1.4591x over previous
#include <cuda_runtime.h>
#include <math.h>
#include <stdint.h>

#define N_NODES 50000
#define N_EDGES 1600000
#define HIDDIM 128
#define NFEAT 128
#define NGAUSS 64

__device__ float g_h[(size_t)N_NODES * NFEAT];
__device__ float g_agg[(size_t)N_NODES * NFEAT];
__device__ float g_tmp[(size_t)N_NODES * HIDDIM];
__device__ int g_perm[N_EDGES + 128];
__device__ int g_ne;      // surviving edge count
__device__ int g_npad;    // padded count (multiple of 128)
__device__ int g_ntiles;  // padded / TEDGE

__device__ __forceinline__ float sspf(float v) {
    return fmaxf(v, 0.0f) + log1pf(expf(-fabsf(v))) - 0.69314718055994531f;
}

__device__ __forceinline__ uint32_t f2tf32(float f) {
    uint32_t r;
    asm("cvt.rna.tf32.f32 %0, %1;" : "=r"(r) : "f"(f));
    return r;
}

__device__ __forceinline__ void mma_tf32(float d[4], const uint32_t a[4],
                                         uint32_t b0, uint32_t b1) {
    asm volatile(
        "mma.sync.aligned.m16n8k8.row.col.f32.tf32.tf32.f32 "
        "{%0,%1,%2,%3}, {%4,%5,%6,%7}, {%8,%9}, {%0,%1,%2,%3};"
        : "+f"(d[0]), "+f"(d[1]), "+f"(d[2]), "+f"(d[3])
        : "r"(a[0]), "r"(a[1]), "r"(a[2]), "r"(a[3]), "r"(b0), "r"(b1));
}

__device__ __forceinline__ void red4(float* p, float v0, float v1, float v2,
                                     float v3) {
    asm volatile("red.global.add.v4.f32 [%0], {%1, %2, %3, %4};" ::"l"(p),
                 "f"(v0), "f"(v1), "f"(v2), "f"(v3)
                 : "memory");
}

__device__ __forceinline__ void gbar(int id) {
    asm volatile("bar.sync %0, 128;" ::"r"(id) : "memory");
}

#define LDA_EA 68
#define LDA_TS 132
#define LDW 136
#define TEDGE 32

// ---------------------------------------------------------------------------
// Cutoff filter: keep edges with 0 <= len <= 10 (others contribute exactly 0).
// Order-preserving within each 256-edge block; blocks placed by one atomicAdd.
// ---------------------------------------------------------------------------
__global__ void reset_count_kernel() {
    if (threadIdx.x == 0) g_ne = 0;
}

__global__ void filter_kernel(const float* __restrict__ elen) {
    __shared__ int wcnt[8];
    __shared__ int wbase[8];
    __shared__ int base;
    const int t = threadIdx.x;
    const int e = blockIdx.x * 256 + t;
    bool keep = false;
    if (e < N_EDGES) {
        float l = elen[e];
        keep = (l <= 10.0f && l >= 0.0f);
    }
    const int lane = t & 31, w = t >> 5;
    unsigned m = __ballot_sync(0xffffffffu, keep);
    if (lane == 0) wcnt[w] = __popc(m);
    __syncthreads();
    if (t == 0) {
        int s = 0;
        for (int i = 0; i < 8; i++) {
            wbase[i] = s;
            s += wcnt[i];
        }
        base = atomicAdd(&g_ne, s);
    }
    __syncthreads();
    if (keep) {
        int pos = base + wbase[w] + __popc(m & ((1u << lane) - 1u));
        g_perm[pos] = e;
    }
}

__global__ void pad_kernel() {
    __shared__ int n0, np;
    if (threadIdx.x == 0) {
        int n = g_ne;
        int npad = (n + 127) & ~127;
        g_npad = npad;
        g_ntiles = npad / TEDGE;
        n0 = n;
        np = npad;
    }
    __syncthreads();
    for (int i = n0 + threadIdx.x; i < np; i += 256) g_perm[i] = -1;
}

// ---------------------------------------------------------------------------
// Node GEMM, tf32 tensor cores
// ---------------------------------------------------------------------------
template <int ACT, int BIAS>
__global__ __launch_bounds__(512) void gemm128_tf32_kernel(
    const float* __restrict__ A, const float* __restrict__ W,
    const float* __restrict__ bias, float* __restrict__ out, int M) {
    extern __shared__ uint32_t smu[];
    uint32_t* As = smu;
    uint32_t* Ws = As + 128 * LDA_TS;
    float* bs = (float*)(Ws + 128 * LDW);

    const int t = threadIdx.x;
    const int row0 = blockIdx.x * 128;
    const int lane = t & 31, warp = t >> 5;
    const int gid = lane >> 2, tid4 = lane & 3;
    const int wr = warp & 3, cg = warp >> 2;
    const int r0 = wr * 32, n0c = cg * 32;

    for (int i = t; i < 128 * 32; i += 512) {
        int r = i >> 5, c4 = i & 31;
        float4 v = ((const float4*)(W + (size_t)r * 128))[c4];
        uint32_t* dst = Ws + r * LDW + c4 * 4;
        dst[0] = f2tf32(v.x);
        dst[1] = f2tf32(v.y);
        dst[2] = f2tf32(v.z);
        dst[3] = f2tf32(v.w);
    }
    for (int i = t; i < 128 * 32; i += 512) {
        int r = i >> 5, c4 = i & 31;
        int rg = row0 + r;
        float4 v = make_float4(0.f, 0.f, 0.f, 0.f);
        if (rg < M) v = ((const float4*)(A + (size_t)rg * 128))[c4];
        uint32_t* dst = As + r * LDA_TS + c4 * 4;
        dst[0] = f2tf32(v.x);
        dst[1] = f2tf32(v.y);
        dst[2] = f2tf32(v.z);
        dst[3] = f2tf32(v.w);
    }
    if (t < 128) bs[t] = BIAS ? bias[t] : 0.0f;
    __syncthreads();

    float acc[2][4][4];
#pragma unroll
    for (int mi = 0; mi < 2; mi++)
#pragma unroll
        for (int ni = 0; ni < 4; ni++) {
            int col = n0c + ni * 8 + 2 * tid4;
            acc[mi][ni][0] = bs[col];
            acc[mi][ni][1] = bs[col + 1];
            acc[mi][ni][2] = bs[col];
            acc[mi][ni][3] = bs[col + 1];
        }
#pragma unroll
    for (int k0 = 0; k0 < 128; k0 += 8) {
        uint32_t afr[2][4];
#pragma unroll
        for (int mi = 0; mi < 2; mi++) {
            int ra = r0 + mi * 16 + gid;
            afr[mi][0] = As[ra * LDA_TS + k0 + tid4];
            afr[mi][1] = As[(ra + 8) * LDA_TS + k0 + tid4];
            afr[mi][2] = As[ra * LDA_TS + k0 + tid4 + 4];
            afr[mi][3] = As[(ra + 8) * LDA_TS + k0 + tid4 + 4];
        }
#pragma unroll
        for (int ni = 0; ni < 4; ni++) {
            int nn = n0c + ni * 8 + gid;
            uint32_t bf0 = Ws[(k0 + tid4) * LDW + nn];
            uint32_t bf1 = Ws[(k0 + tid4 + 4) * LDW + nn];
            mma_tf32(acc[0][ni], afr[0], bf0, bf1);
            mma_tf32(acc[1][ni], afr[1], bf0, bf1);
        }
    }

#pragma unroll
    for (int mi = 0; mi < 2; mi++) {
#pragma unroll
        for (int half = 0; half < 2; half++) {
            int rg = row0 + r0 + mi * 16 + gid + half * 8;
            if (rg >= M) continue;
            float* orow = out + (size_t)rg * 128;
#pragma unroll
            for (int ni = 0; ni < 4; ni++) {
                int col = n0c + ni * 8 + 2 * tid4;
                float v0 = acc[mi][ni][half * 2 + 0];
                float v1 = acc[mi][ni][half * 2 + 1];
                if (ACT == 1) {
                    v0 = sspf(v0);
                    v1 = sspf(v1);
                }
                *(float2*)(orow + col) = make_float2(v0, v1);
            }
        }
    }
}

// ---------------------------------------------------------------------------
// Fused edge kernel: tf32 MMA, 4 independent groups of 4 warps, consuming
// cutoff-surviving edges via g_perm (order-preserving compaction keeps loads
// near-coalesced). Padding entries (-1) get C=0 and contribute exact zeros.
// ---------------------------------------------------------------------------
__global__ __launch_bounds__(512, 1) void edge_fused_kernel(
    const float* __restrict__ edge_attr, const int* __restrict__ eidx,
    const float* __restrict__ elen, const float* __restrict__ w1,
    const float* __restrict__ b1, const float* __restrict__ w2,
    const float* __restrict__ b2) {
    extern __shared__ uint32_t smu[];
    uint32_t* W1s = smu;                         // 64*136
    uint32_t* W2s = W1s + 64 * LDW;              // 128*136
    uint32_t* EAsA = W2s + 128 * LDW;            // 4*32*68
    uint32_t* tssA = EAsA + 4 * TEDGE * LDA_EA;  // 4*32*132
    float* b1s = (float*)(tssA + 4 * TEDGE * LDA_TS);  // 128
    float* b2s = b1s + 128;                            // 128
    float* CsA = b2s + 128;                            // 4*32
    int* ssA = (int*)(CsA + 4 * TEDGE);                // 4*32
    int* dsA = ssA + 4 * TEDGE;                        // 4*32
    int* psA = dsA + 4 * TEDGE;                        // 4*32

    const int t = threadIdx.x;
    const int lane = t & 31, warp = t >> 5;
    const int g = warp >> 2;
    const int w4 = warp & 3;
    const int tg = t & 127;
    const int gid = lane >> 2, tid4 = lane & 3;
    const int n0c = w4 * 32;
    const int* srcp = eidx;
    const int* dstp = eidx + N_EDGES;

    uint32_t* EAs = EAsA + g * TEDGE * LDA_EA;
    uint32_t* tss = tssA + g * TEDGE * LDA_TS;
    float* tssf = (float*)tss;
    float* Cs = CsA + g * TEDGE;
    int* ss = ssA + g * TEDGE;
    int* ds = dsA + g * TEDGE;
    int* ps = psA + g * TEDGE;
    const int bid = 1 + g;

    // One-time weight staging
    for (int i = t; i < 64 * 32; i += 512) {
        int r = i >> 5, c4 = i & 31;
        float4 v = ((const float4*)(w1 + (size_t)r * 128))[c4];
        uint32_t* dstw = W1s + r * LDW + c4 * 4;
        dstw[0] = f2tf32(v.x);
        dstw[1] = f2tf32(v.y);
        dstw[2] = f2tf32(v.z);
        dstw[3] = f2tf32(v.w);
    }
    for (int i = t; i < 128 * 32; i += 512) {
        int r = i >> 5, c4 = i & 31;
        float4 v = ((const float4*)(w2 + (size_t)r * 128))[c4];
        uint32_t* dstw = W2s + r * LDW + c4 * 4;
        dstw[0] = f2tf32(v.x);
        dstw[1] = f2tf32(v.y);
        dstw[2] = f2tf32(v.z);
        dstw[3] = f2tf32(v.w);
    }
    if (t < 128) {
        b1s[t] = b1[t];
        b2s[t] = b2[t];
    }
    const int ntiles = g_ntiles;  // written by pad_kernel before this launch
    __syncthreads();

    const int stride = 4 * gridDim.x;
    for (int tile = blockIdx.x * 4 + g; tile < ntiles; tile += stride) {
        const int e0 = tile * TEDGE;
        gbar(bid);  // prior epilogue readers of this group's smem done

        if (tg < TEDGE) {
            int pe = g_perm[e0 + tg];
            bool valid = pe >= 0;
            int pe2 = valid ? pe : 0;
            ps[tg] = pe2;
            ss[tg] = srcp[pe2];
            ds[tg] = dstp[pe2];
            float l = elen[pe2];
            float c = 0.5f * (cosf(l * 0.31415926535897932f) + 1.0f);
            if (!valid || !(l <= 10.0f && l >= 0.0f)) c = 0.0f;
            Cs[tg] = c;
        }
        gbar(bid);

        // Load edge_attr tile [32][64] via perm (near-sequential rows)
        for (int i = tg; i < TEDGE * 16; i += 128) {
            int r = i >> 4, c4 = i & 15;
            float4 v = ((const float4*)(edge_attr + (size_t)ps[r] * 64))[c4];
            uint32_t* dstw = EAs + r * LDA_EA + c4 * 4;
            dstw[0] = f2tf32(v.x);
            dstw[1] = f2tf32(v.y);
            dstw[2] = f2tf32(v.z);
            dstw[3] = f2tf32(v.w);
        }
        gbar(bid);

        float acc[2][4][4];

        // ---- Stage 1: ts = ssp(EA @ W1 + b1), K=64 ----
#pragma unroll
        for (int mi = 0; mi < 2; mi++)
#pragma unroll
            for (int ni = 0; ni < 4; ni++) {
                int col = n0c + ni * 8 + 2 * tid4;
                acc[mi][ni][0] = b1s[col];
                acc[mi][ni][1] = b1s[col + 1];
                acc[mi][ni][2] = b1s[col];
                acc[mi][ni][3] = b1s[col + 1];
            }
#pragma unroll
        for (int k0 = 0; k0 < 64; k0 += 8) {
            uint32_t afr[2][4];
#pragma unroll
            for (int mi = 0; mi < 2; mi++) {
                int ra = mi * 16 + gid;
                afr[mi][0] = EAs[ra * LDA_EA + k0 + tid4];
                afr[mi][1] = EAs[(ra + 8) * LDA_EA + k0 + tid4];
                afr[mi][2] = EAs[ra * LDA_EA + k0 + tid4 + 4];
                afr[mi][3] = EAs[(ra + 8) * LDA_EA + k0 + tid4 + 4];
            }
#pragma unroll
            for (int ni = 0; ni < 4; ni++) {
                int nn = n0c + ni * 8 + gid;
                uint32_t bf0 = W1s[(k0 + tid4) * LDW + nn];
                uint32_t bf1 = W1s[(k0 + tid4 + 4) * LDW + nn];
                mma_tf32(acc[0][ni], afr[0], bf0, bf1);
                mma_tf32(acc[1][ni], afr[1], bf0, bf1);
            }
        }
#pragma unroll
        for (int mi = 0; mi < 2; mi++) {
            int ra = mi * 16 + gid;
#pragma unroll
            for (int ni = 0; ni < 4; ni++) {
                int col = n0c + ni * 8 + 2 * tid4;
                uint2 lo = make_uint2(f2tf32(sspf(acc[mi][ni][0])),
                                      f2tf32(sspf(acc[mi][ni][1])));
                uint2 hi = make_uint2(f2tf32(sspf(acc[mi][ni][2])),
                                      f2tf32(sspf(acc[mi][ni][3])));
                *(uint2*)(tss + ra * LDA_TS + col) = lo;
                *(uint2*)(tss + (ra + 8) * LDA_TS + col) = hi;
            }
        }
        gbar(bid);

        // ---- Stage 2: W = ts @ W2 + b2, K=128 ----
#pragma unroll
        for (int mi = 0; mi < 2; mi++)
#pragma unroll
            for (int ni = 0; ni < 4; ni++) {
                int col = n0c + ni * 8 + 2 * tid4;
                acc[mi][ni][0] = b2s[col];
                acc[mi][ni][1] = b2s[col + 1];
                acc[mi][ni][2] = b2s[col];
                acc[mi][ni][3] = b2s[col + 1];
            }
#pragma unroll
        for (int k0 = 0; k0 < 128; k0 += 8) {
            uint32_t afr[2][4];
#pragma unroll
            for (int mi = 0; mi < 2; mi++) {
                int ra = mi * 16 + gid;
                afr[mi][0] = tss[ra * LDA_TS + k0 + tid4];
                afr[mi][1] = tss[(ra + 8) * LDA_TS + k0 + tid4];
                afr[mi][2] = tss[ra * LDA_TS + k0 + tid4 + 4];
                afr[mi][3] = tss[(ra + 8) * LDA_TS + k0 + tid4 + 4];
            }
#pragma unroll
            for (int ni = 0; ni < 4; ni++) {
                int nn = n0c + ni * 8 + gid;
                uint32_t bf0 = W2s[(k0 + tid4) * LDW + nn];
                uint32_t bf1 = W2s[(k0 + tid4 + 4) * LDW + nn];
                mma_tf32(acc[0][ni], afr[0], bf0, bf1);
                mma_tf32(acc[1][ni], afr[1], bf0, bf1);
            }
        }
        gbar(bid);  // stage-2 reads of tss done

        // Stage acc*C back into tss (fp32)
#pragma unroll
        for (int mi = 0; mi < 2; mi++) {
            int rA = mi * 16 + gid;
            int rB = rA + 8;
            float CA = Cs[rA], CB = Cs[rB];
#pragma unroll
            for (int ni = 0; ni < 4; ni++) {
                int col = n0c + ni * 8 + 2 * tid4;
                *(float2*)(tssf + rA * LDA_TS + col) =
                    make_float2(acc[mi][ni][0] * CA, acc[mi][ni][1] * CA);
                *(float2*)(tssf + rB * LDA_TS + col) =
                    make_float2(acc[mi][ni][2] * CB, acc[mi][ni][3] * CB);
            }
        }
        gbar(bid);

        // ---- Coalesced epilogue: gather h[src], red4 to agg[dst] ----
#pragma unroll
        for (int it = 0; it < 8; it++) {
            int idx = it * 128 + tg;
            int r = idx >> 5, c4 = idx & 31;
            float4 w4v = *(const float4*)(tssf + r * LDA_TS + c4 * 4);
            const float4 h4 =
                *(const float4*)(g_h + (size_t)ss[r] * 128 + c4 * 4);
            float* arow = g_agg + (size_t)ds[r] * 128 + c4 * 4;
            red4(arow, w4v.x * h4.x, w4v.y * h4.y, w4v.z * h4.z, w4v.w * h4.w);
        }
    }
}

extern "C" void kernel_launch(void* const* d_in, const int* in_sizes, int n_in,
                              void* d_out, int out_size) {
    const float* x = (const float*)d_in[0];
    const int* eidx = (const int*)d_in[1];
    const float* elen = (const float*)d_in[2];
    const float* eattr = (const float*)d_in[3];
    const float* lin1_w = (const float*)d_in[4];
    const float* nn_w1 = (const float*)d_in[5];
    const float* nn_b1 = (const float*)d_in[6];
    const float* nn_w2 = (const float*)d_in[7];
    const float* nn_b2 = (const float*)d_in[8];
    const float* lin2_w = (const float*)d_in[9];
    const float* lin2_b = (const float*)d_in[10];
    const float* lin_w = (const float*)d_in[11];
    const float* lin_b = (const float*)d_in[12];
    float* out = (float*)d_out;

    float *h_p, *agg_p, *tmp_p;
    cudaGetSymbolAddress((void**)&h_p, g_h);
    cudaGetSymbolAddress((void**)&agg_p, g_agg);
    cudaGetSymbolAddress((void**)&tmp_p, g_tmp);

    const size_t ngemm_smem =
        (size_t)(128 * LDA_TS + 128 * LDW) * 4 + 128 * sizeof(float);
    const size_t edge_smem =
        (size_t)(64 * LDW + 128 * LDW + 4 * TEDGE * LDA_EA +
                 4 * TEDGE * LDA_TS) *
            4 +
        (size_t)(2 * 128 + 4 * TEDGE) * sizeof(float) +
        (size_t)(12 * TEDGE) * sizeof(int);

    cudaFuncSetAttribute(gemm128_tf32_kernel<0, 0>,
                         cudaFuncAttributeMaxDynamicSharedMemorySize,
                         (int)ngemm_smem);
    cudaFuncSetAttribute(gemm128_tf32_kernel<1, 1>,
                         cudaFuncAttributeMaxDynamicSharedMemorySize,
                         (int)ngemm_smem);
    cudaFuncSetAttribute(gemm128_tf32_kernel<0, 1>,
                         cudaFuncAttributeMaxDynamicSharedMemorySize,
                         (int)ngemm_smem);
    cudaFuncSetAttribute(edge_fused_kernel,
                         cudaFuncAttributeMaxDynamicSharedMemorySize,
                         (int)edge_smem);

    const int gridN = (N_NODES + 127) / 128;  // 391

    // Cutoff filter -> g_perm (order-preserving compaction), pad to 128
    reset_count_kernel<<<1, 32>>>();
    filter_kernel<<<(N_EDGES + 255) / 256, 256>>>(elen);
    pad_kernel<<<1, 256>>>();

    // h = x @ lin1_w ; agg = 0
    gemm128_tf32_kernel<0, 0><<<gridN, 512, ngemm_smem>>>(x, lin1_w, nullptr,
                                                          h_p, N_NODES);
    cudaMemsetAsync(agg_p, 0, (size_t)N_NODES * NFEAT * sizeof(float));

    // fused edge MLP + envelope + gather/scatter over surviving edges
    edge_fused_kernel<<<148, 512, edge_smem>>>(eattr, eidx, elen, nn_w1, nn_b1,
                                               nn_w2, nn_b2);
    gemm128_tf32_kernel<1, 1><<<gridN, 512, ngemm_smem>>>(agg_p, lin2_w,
                                                          lin2_b, tmp_p,
                                                          N_NODES);
    gemm128_tf32_kernel<0, 1><<<gridN, 512, ngemm_smem>>>(tmp_p, lin_w, lin_b,
                                                          out, N_NODES);
}